// round 1
// baseline (speedup 1.0000x reference)
#include <cuda_runtime.h>

// CrossAttention_47502338294587 — algebraic collapse:
// K/V are broadcast from a single per-batch visual token, so every attention
// logit row is constant -> softmax is exactly uniform -> y == v (broadcast).
// output[b,t,:] = ((vf @ Wv + bv) @ Wp + bp)[b,:]  for every t.
// Independent of x, Wq, bq, Wk, bk.

static constexpr int Cdim = 1024;
static constexpr int Bdim = 4;
static constexpr int Tdim = 1024;

// Scratch (no device allocs allowed; __device__ globals are the sanctioned path)
__device__ float g_vv[Bdim * Cdim];   // vf @ Wv + bv
__device__ float g_row[Bdim * Cdim];  // vv @ Wp + bp

// out[b][c] = bias[c] + sum_k inp[b][k] * W[k][c]
// grid: (Cdim/32, Bdim), block: 256 = 8 warps x 32 lanes.
// Each warp owns a 128-wide k-slice; lanes own 32 consecutive columns
// (coalesced 128B loads of W); smem reduction across the 8 warps.
__global__ void __launch_bounds__(256) gemm4xC_kernel(
    const float* __restrict__ inp,   // [Bdim][Cdim]
    const float* __restrict__ W,     // [Cdim][Cdim] row-major
    const float* __restrict__ bias,  // [Cdim]
    float* __restrict__ outp)        // [Bdim][Cdim]
{
    __shared__ float s_in[Cdim];
    __shared__ float s_red[8][32];

    const int b    = blockIdx.y;
    const int c0   = blockIdx.x * 32;
    const int tid  = threadIdx.x;
    const int lane = tid & 31;
    const int w    = tid >> 5;
    const int c    = c0 + lane;

    // stage the input row (4 KB) into smem
    #pragma unroll
    for (int i = 0; i < Cdim / 256; i++)
        s_in[tid + i * 256] = inp[b * Cdim + tid + i * 256];
    __syncthreads();

    const int kbase = w * (Cdim / 8);   // 128-wide slice per warp
    float acc = 0.f;
    #pragma unroll 8
    for (int kk = 0; kk < Cdim / 8; kk++) {
        const int k = kbase + kk;
        acc = fmaf(s_in[k], W[k * Cdim + c], acc);
    }
    s_red[w][lane] = acc;
    __syncthreads();

    if (w == 0) {
        float sum = bias[c];
        #pragma unroll
        for (int j = 0; j < 8; j++) sum += s_red[j][lane];
        outp[b * Cdim + c] = sum;
    }
}

// out[b][t][c] = g_row[b][c], vectorized float4. grid covers B*T*C/4 lanes.
__global__ void __launch_bounds__(256) bcast_kernel(float* __restrict__ out)
{
    const int idx = blockIdx.x * 256 + threadIdx.x;  // 0 .. B*T*C/4-1
    const int c4  = idx & (Cdim / 4 - 1);            // column group
    const int bt  = idx >> 8;                        // / (C/4)
    const int b   = bt >> 10;                        // / T
    const float4 v = reinterpret_cast<const float4*>(g_row)[b * (Cdim / 4) + c4];
    reinterpret_cast<float4*>(out)[idx] = v;
}

extern "C" void kernel_launch(void* const* d_in, const int* in_sizes, int n_in,
                              void* d_out, int out_size)
{
    (void)in_sizes; (void)n_in;
    const float* vf = (const float*)d_in[1];  // visual_features [B,C]
    const float* Wv = (const float*)d_in[6];
    const float* bv = (const float*)d_in[7];
    const float* Wp = (const float*)d_in[8];
    const float* bp = (const float*)d_in[9];
    float* out = (float*)d_out;

    float *p_vv = nullptr, *p_row = nullptr;
    cudaGetSymbolAddress((void**)&p_vv, g_vv);
    cudaGetSymbolAddress((void**)&p_row, g_row);

    dim3 ggrid(Cdim / 32, Bdim);
    gemm4xC_kernel<<<ggrid, 256>>>(vf, Wv, bv, p_vv);    // vv = vf@Wv + bv
    gemm4xC_kernel<<<ggrid, 256>>>(p_vv, Wp, bp, p_row); // row = vv@Wp + bp

    const int total4 = Bdim * Tdim * Cdim / 4;           // 1,048,576
    bcast_kernel<<<total4 / 256, 256>>>(out);

    (void)out_size;
}

// round 3
// speedup vs baseline: 1.2505x; 1.2505x over previous
#include <cuda_runtime.h>

// CrossAttention_47502338294587 — algebraic collapse:
// K/V come from a single per-batch visual token broadcast over T, so every
// attention-logit row is constant -> softmax is exactly uniform -> y == v.
// output[b,t,:] = ((vf @ Wv + bv) @ Wp + bp)[b,:]   (independent of x,Wq,Wk).
//
// 3 launches, all deterministic (no atomics):
//  L1 gemm_part<0>: partial sums of vf@Wv per k-split  -> g_part1
//  L2 gemm_part<1>: folds (bv + sum part1) as input, partials of @Wp -> g_part2
//  L3 bcast:        row = bp + sum part2, broadcast to all T, float4 full-line

static constexpr int C = 1024;
static constexpr int B = 4;
static constexpr int T = 1024;
static constexpr int KSPLIT = 4;
static constexpr int KRANGE = C / KSPLIT;   // 256
static constexpr int CG = 32;               // columns per block (one 128B line)
static constexpr int NCG = C / CG;          // 32 column groups
static constexpr int F4PB = CG / 4;         // 8 float4 per row per block

__device__ float4 g_part1[KSPLIT * B * (C / 4)];   // 64 KB
__device__ float4 g_part2[KSPLIT * B * (C / 4)];   // 64 KB

// MODE 0: in = vf [B][C].  MODE 1: in = bv [C], input row = bv + sum_s part1.
// Block (cg, ks): cols [cg*32, cg*32+32), k in [ks*256, ks*256+256).
// Warp LDG: lanes = 8 float4 x 4 k-rows -> 4 full 128B lines per LDG.
template <int MODE>
__global__ void __launch_bounds__(256) gemm_part(
    const float* __restrict__ in,
    const float* __restrict__ W,
    float4* __restrict__ part_out)
{
    __shared__ float  s_in[B][KRANGE];      // 4 KB
    __shared__ float4 s_red[256][B];        // 16 KB

    const int cg = blockIdx.x;              // 0..31
    const int ks = blockIdx.y;              // 0..3
    const int t  = threadIdx.x;
    const int f4 = t & 7;                   // float4 column within block
    const int kr = t >> 3;                  // 0..31 k sub-row
    const int kbase = ks * KRANGE;

    // Stage this k-range of the input rows for all 4 batches (fold partials in MODE 1)
    {
        const int k = t;                    // 0..255
        const float* __restrict__ p1 = (const float*)g_part1;
        #pragma unroll
        for (int b = 0; b < B; b++) {
            float v;
            if (MODE == 0) {
                v = in[b * C + kbase + k];
            } else {
                v = in[kbase + k];          // bias bv[k]
                #pragma unroll
                for (int s = 0; s < KSPLIT; s++)
                    v += p1[((s * B + b) * C) + kbase + k];
            }
            s_in[b][k] = v;
        }
    }
    __syncthreads();

    float4 acc[B];
    #pragma unroll
    for (int b = 0; b < B; b++) acc[b] = make_float4(0.f, 0.f, 0.f, 0.f);

    const float4* W4 = (const float4*)W;
    #pragma unroll
    for (int step = 0; step < KRANGE / 32; step++) {    // 8 independent LDG.128
        const int k = kr + step * 32;
        const float4 w = W4[(size_t)(kbase + k) * (C / 4) + cg * F4PB + f4];
        #pragma unroll
        for (int b = 0; b < B; b++) {
            const float s = s_in[b][k];
            acc[b].x = fmaf(s, w.x, acc[b].x);
            acc[b].y = fmaf(s, w.y, acc[b].y);
            acc[b].z = fmaf(s, w.z, acc[b].z);
            acc[b].w = fmaf(s, w.w, acc[b].w);
        }
    }

    #pragma unroll
    for (int b = 0; b < B; b++) s_red[t][b] = acc[b];
    __syncthreads();

    // tree-reduce over kr (threads sharing f4 are t = f4 + 8*kr)
    #pragma unroll
    for (int off = 16; off > 0; off >>= 1) {
        if (kr < off) {
            #pragma unroll
            for (int b = 0; b < B; b++) {
                float4 a = s_red[t][b];
                const float4 o = s_red[t + off * 8][b];
                a.x += o.x; a.y += o.y; a.z += o.z; a.w += o.w;
                s_red[t][b] = a;
            }
        }
        __syncthreads();
    }

    if (t < F4PB) {
        #pragma unroll
        for (int b = 0; b < B; b++)
            part_out[(ks * B + b) * (C / 4) + cg * F4PB + t] = s_red[t][b];
    }
}

// grid = B * (T/8) = 512 blocks; block handles (b, 8 consecutive t rows).
// Each thread owns one float4 column: row value stays in registers,
// 8 fully-coalesced full-line STG.128 per thread.
__global__ void __launch_bounds__(256) bcast_kernel(
    const float* __restrict__ bp, float* __restrict__ out)
{
    const int b   = blockIdx.x >> 7;        // /128
    const int tch = blockIdx.x & 127;       // t-chunk of 8
    const int t   = threadIdx.x;            // float4 column 0..255

    float4 r = ((const float4*)bp)[t];
    #pragma unroll
    for (int s = 0; s < KSPLIT; s++) {
        const float4 p = g_part2[(s * B + b) * (C / 4) + t];
        r.x += p.x; r.y += p.y; r.z += p.z; r.w += p.w;
    }

    float4* o4 = (float4*)out + ((size_t)b * T + tch * 8) * (C / 4);
    #pragma unroll
    for (int tt = 0; tt < 8; tt++)
        o4[tt * (C / 4) + t] = r;
}

extern "C" void kernel_launch(void* const* d_in, const int* in_sizes, int n_in,
                              void* d_out, int out_size)
{
    (void)in_sizes; (void)n_in; (void)out_size;
    const float* vf = (const float*)d_in[1];  // visual_features [B,C]
    const float* Wv = (const float*)d_in[6];
    const float* bv = (const float*)d_in[7];
    const float* Wp = (const float*)d_in[8];
    const float* bp = (const float*)d_in[9];
    float* out = (float*)d_out;

    float4 *p1 = nullptr, *p2 = nullptr;
    cudaGetSymbolAddress((void**)&p1, g_part1);
    cudaGetSymbolAddress((void**)&p2, g_part2);

    dim3 g(NCG, KSPLIT);                           // 32 x 4 = 128 blocks
    gemm_part<0><<<g, 256>>>(vf, Wv, p1);          // partials of vf@Wv
    gemm_part<1><<<g, 256>>>(bv, Wp, p2);          // folds +bv, partials of @Wp
    bcast_kernel<<<B * (T / 8), 256>>>(bp, out);   // 512 blocks
}